// round 2
// baseline (speedup 1.0000x reference)
#include <cuda_runtime.h>
#include <math.h>
#include <stdint.h>

#define BDIM 4
#define TDIM 8192
#define CDIM 1024
#define EDIM 64
#define NTOK (BDIM*TDIM)      // 32768 tokens
#define KTOP 2

typedef unsigned long long ull;

// packed fp32x2 FMA: d = a*b + d (elementwise on packed halves)
#define FMA2(d, a, b) asm("fma.rn.f32x2 %0, %1, %2, %0;" : "+l"(d) : "l"(a), "l"(b))

// -------- device scratch (no allocations allowed) --------
__device__ float        g_M1T[CDIM*EDIM];     // folded weights, [d][e]
__device__ float        g_hcond[BDIM*CDIM];   // cond @ Wc[:,C:]^T
__device__ float        g_bias[BDIM*EDIM];    // hcond @ Wg^T
__device__ float        g_imp_parts[8][EDIM];
__device__ unsigned int g_cnt_parts[8][EDIM];

// -------- zero scratch --------
__global__ void zero_kernel() {
    int i = blockIdx.x * blockDim.x + threadIdx.x;
    if (i < CDIM*EDIM) g_M1T[i] = 0.0f;
    if (i < 8*EDIM) {
        (&g_imp_parts[0][0])[i] = 0.0f;
        (&g_cnt_parts[0][0])[i] = 0u;
    }
}

// -------- hcond[b][c] = sum_d cond[b][d] * Wc[c][C+d] --------
__global__ void hcond_kernel(const float* __restrict__ cond,
                             const float* __restrict__ Wc) {
    int warp = (blockIdx.x * blockDim.x + threadIdx.x) >> 5;
    int lane = threadIdx.x & 31;
    if (warp >= BDIM*CDIM) return;
    int b = warp >> 10;
    int c = warp & (CDIM-1);
    const float* crow = cond + b * CDIM;
    const float* wrow = Wc + (size_t)c * (2*CDIM) + CDIM;
    float acc = 0.0f;
    for (int d = lane; d < CDIM; d += 32)
        acc = fmaf(crow[d], wrow[d], acc);
    #pragma unroll
    for (int off = 16; off; off >>= 1)
        acc += __shfl_xor_sync(0xffffffffu, acc, off);
    if (lane == 0) g_hcond[b*CDIM + c] = acc;
}

// -------- bias[b][e] = sum_c hcond[b][c] * Wg[e][c] --------
__global__ void bias_kernel(const float* __restrict__ Wg) {
    int warp = (blockIdx.x * blockDim.x + threadIdx.x) >> 5;
    int lane = threadIdx.x & 31;
    if (warp >= BDIM*EDIM) return;
    int b = warp >> 6;
    int e = warp & (EDIM-1);
    const float* h = g_hcond + b * CDIM;
    const float* w = Wg + (size_t)e * CDIM;
    float acc = 0.0f;
    for (int c = lane; c < CDIM; c += 32)
        acc = fmaf(h[c], w[c], acc);
    #pragma unroll
    for (int off = 16; off; off >>= 1)
        acc += __shfl_xor_sync(0xffffffffu, acc, off);
    if (lane == 0) g_bias[b*EDIM + e] = acc;
}

// -------- M1T[d][e] = sum_c Wg[e][c] * Wc[c][d],  d < C --------
// grid (16 d-tiles, 16 c-splits of 64), 256 threads.
__global__ __launch_bounds__(256) void m1_kernel(const float* __restrict__ Wg,
                                                 const float* __restrict__ Wc) {
    __shared__ float sWgT[64][68];  // [c][e]
    __shared__ float sWc [64][68];  // [c][d]
    int d0 = blockIdx.x * 64;
    int c0 = blockIdx.y * 64;
    int tid = threadIdx.x;
    int ex = (tid & 15) * 4;        // 4 experts
    int dx = (tid >> 4) * 4;        // 4 d-columns

    {   // Wg chunk, transposed into smem
        int e = tid >> 2;
        int j = (tid & 3) * 16;
        const float* src = Wg + (size_t)e * CDIM + c0 + j;
        #pragma unroll
        for (int i = 0; i < 16; i += 4) {
            float4 v = *(const float4*)(src + i);
            sWgT[j+i+0][e] = v.x; sWgT[j+i+1][e] = v.y;
            sWgT[j+i+2][e] = v.z; sWgT[j+i+3][e] = v.w;
        }
    }
    {   // Wc chunk, direct copy
        int c = tid >> 2;
        int j = (tid & 3) * 16;
        const float* src = Wc + (size_t)(c0 + c) * (2*CDIM) + d0 + j;
        #pragma unroll
        for (int i = 0; i < 16; i += 4)
            *(float4*)&sWc[c][j+i] = *(const float4*)(src + i);
    }
    __syncthreads();

    float acc[4][4] = {};
    #pragma unroll 8
    for (int c = 0; c < 64; c++) {
        float4 g = *(const float4*)&sWgT[c][ex];
        float4 w = *(const float4*)&sWc[c][dx];
        float gg[4] = {g.x, g.y, g.z, g.w};
        float ww[4] = {w.x, w.y, w.z, w.w};
        #pragma unroll
        for (int i = 0; i < 4; i++)
            #pragma unroll
            for (int j = 0; j < 4; j++)
                acc[i][j] = fmaf(gg[i], ww[j], acc[i][j]);
    }
    #pragma unroll
    for (int j = 0; j < 4; j++)
        #pragma unroll
        for (int i = 0; i < 4; i++)
            atomicAdd(&g_M1T[(size_t)(d0 + dx + j) * EDIM + ex + i], acc[i][j]);
}

// -------- main fused kernel: logits GEMM (f32x2) + softmax + top2 + stats ----
// 64 tokens x 64 experts per block, 128 threads, k-chunks of 32.
// Per-thread: 4 tokens x 8 experts = 16 packed f32x2 accumulators.
#define KC 32
#define SXD_STRIDE 66           // ull row stride (528B: 16B-aligned, 2-way STS)
#define SMF_STRIDE 68           // float row stride (272B: 16B-aligned)

__global__ __launch_bounds__(128) void router_main(const float* __restrict__ x,
                                                   float* __restrict__ out) {
    __shared__ __align__(16) char sbuf[KC*SXD_STRIDE*8 + KC*SMF_STRIDE*4];
    ull*   sxd = (ull*)sbuf;                              // [KC][66]: dup x pairs, [k][t]
    float* smf = (float*)(sbuf + KC*SXD_STRIDE*8);        // [KC][68]: M1T tile, [k][e]
    float* slog = (float*)sbuf;                           // reused post-GEMM: [64][68] logits
    __shared__ float simp[64];
    __shared__ unsigned scnt[64];

    int tid  = threadIdx.x;
    int tok0 = blockIdx.x * 64;
    int b    = tok0 >> 13;

    if (tid < 64) { simp[tid] = 0.0f; scnt[tid] = 0u; }

    int tx = (tid & 15) * 4;        // token group (4 tokens)
    int ex = (tid >> 4) * 8;        // expert group (8 experts = 4 pairs)

    // accumulators init = bias (broadcast over tokens)
    ull acc[4][4];
    {
        const ull* bp = (const ull*)(g_bias + b*EDIM + ex);
        ull b0 = bp[0], b1 = bp[1], b2 = bp[2], b3 = bp[3];
        #pragma unroll
        for (int i = 0; i < 4; i++) {
            acc[i][0] = b0; acc[i][1] = b1; acc[i][2] = b2; acc[i][3] = b3;
        }
    }

    // loader assignments
    int lt = tid >> 1;              // x loader: token 0..63
    int lk = (tid & 1) * 16;        // x loader: k-half offset
    int mk = tid >> 2;              // m loader: k row 0..31
    int mj = (tid & 3) * 16;        // m loader: e offset

    const float* xbase = x + (size_t)(tok0 + lt) * CDIM + lk;
    const float* mbase = g_M1T + (size_t)mk * EDIM + mj;

    for (int k0 = 0; k0 < CDIM; k0 += KC) {
        // load x chunk, write transposed + duplicated: sxd[k][t] = {x,x}
        #pragma unroll
        for (int c4 = 0; c4 < 4; c4++) {
            float4 v = *(const float4*)(xbase + k0 + c4*4);
            int kr = lk + c4*4;
            *(float2*)(sxd + (size_t)(kr+0)*SXD_STRIDE + lt) = make_float2(v.x, v.x);
            *(float2*)(sxd + (size_t)(kr+1)*SXD_STRIDE + lt) = make_float2(v.y, v.y);
            *(float2*)(sxd + (size_t)(kr+2)*SXD_STRIDE + lt) = make_float2(v.z, v.z);
            *(float2*)(sxd + (size_t)(kr+3)*SXD_STRIDE + lt) = make_float2(v.w, v.w);
        }
        // load m chunk: smf[k][e]
        #pragma unroll
        for (int i = 0; i < 16; i += 4)
            *(float4*)(smf + (size_t)mk*SMF_STRIDE + mj + i) =
                *(const float4*)(mbase + (size_t)k0*EDIM + i);
        __syncthreads();

        #pragma unroll
        for (int k = 0; k < KC; k++) {
            ulonglong2 xa = *(const ulonglong2*)(sxd + (size_t)k*SXD_STRIDE + tx);
            ulonglong2 xb = *(const ulonglong2*)(sxd + (size_t)k*SXD_STRIDE + tx + 2);
            ulonglong2 ma = *(const ulonglong2*)(smf + (size_t)k*SMF_STRIDE + ex);
            ulonglong2 mb = *(const ulonglong2*)(smf + (size_t)k*SMF_STRIDE + ex + 4);
            FMA2(acc[0][0], xa.x, ma.x); FMA2(acc[0][1], xa.x, ma.y);
            FMA2(acc[0][2], xa.x, mb.x); FMA2(acc[0][3], xa.x, mb.y);
            FMA2(acc[1][0], xa.y, ma.x); FMA2(acc[1][1], xa.y, ma.y);
            FMA2(acc[1][2], xa.y, mb.x); FMA2(acc[1][3], xa.y, mb.y);
            FMA2(acc[2][0], xb.x, ma.x); FMA2(acc[2][1], xb.x, ma.y);
            FMA2(acc[2][2], xb.x, mb.x); FMA2(acc[2][3], xb.x, mb.y);
            FMA2(acc[3][0], xb.y, ma.x); FMA2(acc[3][1], xb.y, ma.y);
            FMA2(acc[3][2], xb.y, mb.x); FMA2(acc[3][3], xb.y, mb.y);
        }
        __syncthreads();
    }

    // unpack logits into smem (reuse sbuf as slog[64][68])
    #pragma unroll
    for (int i = 0; i < 4; i++) {
        float2 p0 = *(float2*)&acc[i][0];
        float2 p1 = *(float2*)&acc[i][1];
        float2 p2 = *(float2*)&acc[i][2];
        float2 p3 = *(float2*)&acc[i][3];
        float* row = slog + (size_t)(tx + i) * SMF_STRIDE + ex;
        *(float4*)(row)     = make_float4(p0.x, p0.y, p1.x, p1.y);
        *(float4*)(row + 4) = make_float4(p2.x, p2.y, p3.x, p3.y);
    }
    __syncthreads();

    // epilogue: 4 warps x 16 tokens; lane covers experts {l, l+32}
    int warp = tid >> 5, lane = tid & 31;
    float* out_idx = out;
    float* out_sc  = out + (size_t)NTOK * KTOP;
    float* out_pr  = out + (size_t)2 * NTOK * KTOP;
    const float NEG_INF = __int_as_float(0xff800000);

    float impL0 = 0.0f, impL1 = 0.0f;
    for (int tt = warp * 16; tt < warp * 16 + 16; tt++) {
        float v0 = slog[(size_t)tt * SMF_STRIDE + lane];
        float v1 = slog[(size_t)tt * SMF_STRIDE + lane + 32];
        // softmax over 64
        float m = fmaxf(v0, v1);
        #pragma unroll
        for (int off = 16; off; off >>= 1)
            m = fmaxf(m, __shfl_xor_sync(0xffffffffu, m, off));
        float e0 = expf(v0 - m), e1 = expf(v1 - m);
        float s = e0 + e1;
        #pragma unroll
        for (int off = 16; off; off >>= 1)
            s += __shfl_xor_sync(0xffffffffu, s, off);
        float inv = 1.0f / s;
        float p0 = e0 * inv, p1 = e1 * inv;
        int gt = tok0 + tt;
        out_pr[(size_t)gt * EDIM + lane]      = p0;
        out_pr[(size_t)gt * EDIM + lane + 32] = p1;
        impL0 += p0; impL1 += p1;

        // top-1 (ties -> lower index, matching jax top_k)
        float rv; int ri;
        if (v0 >= v1) { rv = v0; ri = lane; } else { rv = v1; ri = lane + 32; }
        #pragma unroll
        for (int off = 16; off; off >>= 1) {
            float ov = __shfl_xor_sync(0xffffffffu, rv, off);
            int   oi = __shfl_xor_sync(0xffffffffu, ri, off);
            if (ov > rv || (ov == rv && oi < ri)) { rv = ov; ri = oi; }
        }
        int i1st = ri; float v1st = rv;
        // top-2: mask out the winning slot only
        float c0 = (lane      == i1st) ? NEG_INF : v0;
        float c1 = (lane + 32 == i1st) ? NEG_INF : v1;
        if (c0 >= c1) { rv = c0; ri = lane; } else { rv = c1; ri = lane + 32; }
        #pragma unroll
        for (int off = 16; off; off >>= 1) {
            float ov = __shfl_xor_sync(0xffffffffu, rv, off);
            int   oi = __shfl_xor_sync(0xffffffffu, ri, off);
            if (ov > rv || (ov == rv && oi < ri)) { rv = ov; ri = oi; }
        }
        int i2nd = ri; float v2nd = rv;

        if (lane == 0) {
            float ee = expf(v2nd - v1st);   // softmax over the top-2 pair
            float d  = 1.0f + ee;
            out_idx[gt*2 + 0] = (float)i1st;
            out_idx[gt*2 + 1] = (float)i2nd;
            out_sc [gt*2 + 0] = 1.0f / d;
            out_sc [gt*2 + 1] = ee / d;
            atomicAdd(&scnt[i1st], 1u);
            atomicAdd(&scnt[i2nd], 1u);
        }
    }
    atomicAdd(&simp[lane],      impL0);
    atomicAdd(&simp[lane + 32], impL1);
    __syncthreads();
    if (tid < 64) {
        atomicAdd(&g_imp_parts[blockIdx.x & 7][tid], simp[tid]);
        atomicAdd(&g_cnt_parts[blockIdx.x & 7][tid], scnt[tid]);
    }
}

// -------- finalize importance / load --------
__global__ void finalize_kernel(float* __restrict__ out) {
    int e = threadIdx.x;
    if (e >= EDIM) return;
    float imp = 0.0f;
    unsigned cnt = 0;
    #pragma unroll
    for (int p = 0; p < 8; p++) {
        imp += g_imp_parts[p][e];
        cnt += g_cnt_parts[p][e];
    }
    size_t base = (size_t)2 * NTOK * KTOP + (size_t)NTOK * EDIM;
    out[base + e]        = imp / (float)NTOK;                 // importance
    out[base + EDIM + e] = (float)cnt / (float)(NTOK * KTOP); // load
}

extern "C" void kernel_launch(void* const* d_in, const int* in_sizes, int n_in,
                              void* d_out, int out_size) {
    const float* x    = (const float*)d_in[0];
    const float* cond = (const float*)d_in[1];
    const float* Wg   = (const float*)d_in[2];
    const float* Wc   = (const float*)d_in[3];
    float* out = (float*)d_out;
    (void)in_sizes; (void)n_in; (void)out_size;

    zero_kernel   <<<(CDIM*EDIM + 255) / 256, 256>>>();
    hcond_kernel  <<<(BDIM*CDIM * 32) / 256, 256>>>(cond, Wc);
    bias_kernel   <<<(BDIM*EDIM * 32 + 255) / 256, 256>>>(Wg);
    m1_kernel     <<<dim3(16, 16), 256>>>(Wg, Wc);
    router_main   <<<NTOK / 64, 128>>>(x, out);
    finalize_kernel<<<1, 64>>>(out);
}